// round 12
// baseline (speedup 1.0000x reference)
#include <cuda_runtime.h>
#include <cuda_bf16.h>
#include <math.h>

// Problem constants
#define BB 2
#define LL 2048
#define DD 2048
#define NN 16
#define KX 96          // DT_RANK + 2*D_STATE
#define NCH 64         // chunks along L
#define CH 32          // chunk length (NCH*CH == LL)

typedef unsigned long long u64;

// ---------------- scratch (device globals) ----------------
__device__ __align__(16) float g_xpart[8][BB * LL * KX];    // gemm1 K-split partials
__device__ __align__(16) float g_xdbl[BB * LL * KX];
__device__ __align__(16) float g_dt[BB * LL * DD];
__device__ __align__(16) float g_hf[BB * NCH * DD * NN];
__device__ __align__(16) float g_h0[BB * NCH * DD * NN];
__device__ __align__(16) float g_sdt[BB * NCH * DD];

// ---------------- f32x2 helpers ----------------
__device__ __forceinline__ u64 pk2(float lo, float hi) {
    u64 r; asm("mov.b64 %0,{%1,%2};" : "=l"(r) : "f"(lo), "f"(hi)); return r;
}
__device__ __forceinline__ void unpk2(u64 v, float& lo, float& hi) {
    asm("mov.b64 {%0,%1},%2;" : "=f"(lo), "=f"(hi) : "l"(v));
}
__device__ __forceinline__ u64 fma2(u64 a, u64 b, u64 c) {
    u64 d; asm("fma.rn.f32x2 %0,%1,%2,%3;" : "=l"(d) : "l"(a), "l"(b), "l"(c)); return d;
}
__device__ __forceinline__ u64 mul2(u64 a, u64 b) {
    u64 d; asm("mul.rn.f32x2 %0,%1,%2;" : "=l"(d) : "l"(a), "l"(b)); return d;
}

// ================= GEMM1 (K-split x8): 128-row tiles, micro 4rp x 6c, double-buffered, k-tile 16 =================
__global__ void __launch_bounds__(256) k_gemm1(const float* __restrict__ u,
                                               const float* __restrict__ Wx) {
    __shared__ __align__(16) u64 us2[2][16][65];
    __shared__ __align__(16) u64 ws2[2][16][97];
    const int r0 = blockIdx.x * 128;
    const int kbeg = blockIdx.y * 256;
    const int tid = threadIdx.x;
    const int tx = tid & 15, ty = tid >> 4;

    u64 acc[4][6];
#pragma unroll
    for (int i = 0; i < 4; i++)
#pragma unroll
        for (int j = 0; j < 6; j++) acc[i][j] = 0ull;

    auto stage = [&](int k0, int buf) {
        {
            int rp = tid >> 2;
            int kq = (tid & 3) * 4;
            const float4 a0 = *(const float4*)&u[(size_t)(r0 + 2 * rp) * 2048 + k0 + kq];
            const float4 a1 = *(const float4*)&u[(size_t)(r0 + 2 * rp + 1) * 2048 + k0 + kq];
            us2[buf][kq + 0][rp] = pk2(a0.x, a1.x);
            us2[buf][kq + 1][rp] = pk2(a0.y, a1.y);
            us2[buf][kq + 2][rp] = pk2(a0.z, a1.z);
            us2[buf][kq + 3][rp] = pk2(a0.w, a1.w);
        }
#pragma unroll
        for (int p = 0; p < 2; p++) {
            int g = tid + p * 256;
            if (g < 384) {
                int c = g >> 2;
                int kw = (g & 3) * 4;
                float4 w = *(const float4*)&Wx[(size_t)c * 2048 + k0 + kw];
                ws2[buf][kw + 0][c] = pk2(w.x, w.x);
                ws2[buf][kw + 1][c] = pk2(w.y, w.y);
                ws2[buf][kw + 2][c] = pk2(w.z, w.z);
                ws2[buf][kw + 3][c] = pk2(w.w, w.w);
            }
        }
    };

    stage(kbeg, 0);
    __syncthreads();
#pragma unroll
    for (int kt = 0; kt < 16; kt++) {
        if (kt < 15) stage(kbeg + (kt + 1) * 16, (kt + 1) & 1);
        const int buf = kt & 1;
#pragma unroll
        for (int k = 0; k < 16; k++) {
            u64 ua[4];
#pragma unroll
            for (int i = 0; i < 4; i++) ua[i] = us2[buf][k][ty * 4 + i];
#pragma unroll
            for (int j = 0; j < 6; j++) {
                u64 w2 = ws2[buf][k][tx * 6 + j];
#pragma unroll
                for (int i = 0; i < 4; i++) acc[i][j] = fma2(ua[i], w2, acc[i][j]);
            }
        }
        __syncthreads();
    }
    float* dst = g_xpart[blockIdx.y];
#pragma unroll
    for (int i = 0; i < 4; i++)
#pragma unroll
        for (int j = 0; j < 6; j++) {
            float lo, hi; unpk2(acc[i][j], lo, hi);
            int row = r0 + ty * 8 + 2 * i;
            int col = tx * 6 + j;
            dst[row * KX + col] = lo;
            dst[(row + 1) * KX + col] = hi;
        }
}

// ================= reduce the 8 partials (deterministic) =================
__global__ void __launch_bounds__(256) k_red1() {
    int idx = blockIdx.x * 256 + threadIdx.x;
    float4 s = ((const float4*)g_xpart[0])[idx];
#pragma unroll
    for (int p = 1; p < 8; p++) {
        float4 a = ((const float4*)g_xpart[p])[idx];
        s.x += a.x; s.y += a.y; s.z += a.z; s.w += a.w;
    }
    ((float4*)g_xdbl)[idx] = s;
}

// ========= GEMM2: 128x128 tile, micro 4rp x 8c =========
__global__ void __launch_bounds__(256) k_gemm2(const float* __restrict__ Wdt,
                                               const float* __restrict__ bdt) {
    __shared__ __align__(16) u64   us2[64][65];
    __shared__ __align__(16) float ws[64][128];
    const int r0 = blockIdx.x * 128;
    const int c0 = blockIdx.y * 128;
    const int tid = threadIdx.x;
    const int tx = tid & 15, ty = tid >> 4;

#pragma unroll
    for (int p = 0; p < 4; p++) {
        int g = tid + p * 256;
        int rp = g >> 4;
        int kq = (g & 15) * 4;
        const float4 a0 = *(const float4*)&g_xdbl[(r0 + 2 * rp) * KX + kq];
        const float4 a1 = *(const float4*)&g_xdbl[(r0 + 2 * rp + 1) * KX + kq];
        us2[kq + 0][rp] = pk2(a0.x, a1.x);
        us2[kq + 1][rp] = pk2(a0.y, a1.y);
        us2[kq + 2][rp] = pk2(a0.z, a1.z);
        us2[kq + 3][rp] = pk2(a0.w, a1.w);
    }
#pragma unroll
    for (int p = 0; p < 8; p++) {
        int g = tid + p * 256;
        int c = g & 127;
        int kq = (g >> 7) * 4;
        float4 w = *(const float4*)&Wdt[(size_t)(c0 + c) * 64 + kq];
        ws[kq + 0][c] = w.x;
        ws[kq + 1][c] = w.y;
        ws[kq + 2][c] = w.z;
        ws[kq + 3][c] = w.w;
    }
    __syncthreads();

    u64 acc[4][8];
#pragma unroll
    for (int i = 0; i < 4; i++)
#pragma unroll
        for (int j = 0; j < 8; j++) acc[i][j] = 0ull;

#pragma unroll 8
    for (int k = 0; k < 64; k++) {
        u64 ua[4];
#pragma unroll
        for (int i = 0; i < 4; i++) ua[i] = us2[k][ty * 4 + i];
        float4 wa = *(const float4*)&ws[k][tx * 8];
        float4 wb = *(const float4*)&ws[k][tx * 8 + 4];
        u64 w2[8] = {pk2(wa.x, wa.x), pk2(wa.y, wa.y), pk2(wa.z, wa.z), pk2(wa.w, wa.w),
                     pk2(wb.x, wb.x), pk2(wb.y, wb.y), pk2(wb.z, wb.z), pk2(wb.w, wb.w)};
#pragma unroll
        for (int j = 0; j < 8; j++)
#pragma unroll
            for (int i = 0; i < 4; i++) acc[i][j] = fma2(ua[i], w2[j], acc[i][j]);
    }

    float bb[8];
#pragma unroll
    for (int j = 0; j < 8; j++) bb[j] = bdt[c0 + tx * 8 + j];

#pragma unroll
    for (int i = 0; i < 4; i++)
#pragma unroll
        for (int j = 0; j < 8; j++) {
            float lo, hi; unpk2(acc[i][j], lo, hi);
            int row = r0 + ty * 8 + 2 * i;
            int col = c0 + tx * 8 + j;
            float x0 = lo + bb[j];
            float x1 = hi + bb[j];
            float s0 = fmaxf(x0, 0.f) + __logf(1.f + __expf(-fabsf(x0)));
            float s1 = fmaxf(x1, 0.f) + __logf(1.f + __expf(-fabsf(x1)));
            g_dt[(size_t)row * DD + col] = s0;
            g_dt[(size_t)(row + 1) * DD + col] = s1;
        }
}

// ---------------- per-half A setup + structure check ----------------
// Thread owns n = half*8 .. half*8+7 of state dim for its d. Checks its half
// against A[n] = (n+1)*A0 with A0 = A[d][0].
__device__ __forceinline__ bool load_A_half(const float* __restrict__ A_log, int d, int half,
                                            float& A0, float Av[8]) {
    float a0 = -__expf(__ldg(A_log + d * 16));
#pragma unroll
    for (int q = 0; q < 8; q += 4) {
        float4 a4 = *(const float4*)&A_log[d * 16 + half * 8 + q];
        Av[q]     = -__expf(a4.x);
        Av[q + 1] = -__expf(a4.y);
        Av[q + 2] = -__expf(a4.z);
        Av[q + 3] = -__expf(a4.w);
    }
    bool ok = (a0 < 0.f);
#pragma unroll
    for (int q = 0; q < 8; q++) {
        float tgt = (float)(half * 8 + q + 1) * a0;
        ok = ok && (fabsf(Av[q] - tgt) <= 4e-6f * fabsf(tgt));
    }
    A0 = a0;
    return ok;
}

// ================= Scan phase A: n-split across half-warps (lane i <-> i+16 share d) =================
__global__ void __launch_bounds__(256) k_scanA(const float* __restrict__ u,
                                               const float* __restrict__ A_log) {
    __shared__ __align__(16) float sB[CH][16];
    const int b = blockIdx.z, c = blockIdx.y;
    const int tid = threadIdx.x;
    const int lane = tid & 31, wid = tid >> 5;
    const int half = lane >> 4;               // 0: n=0..7, 1: n=8..15
    const int d = blockIdx.x * 128 + wid * 16 + (lane & 15);
    const int l0 = c * CH;

#pragma unroll
    for (int p = 0; p < 2; p++) {
        int idx = tid + p * 256;
        int t = idx >> 4, j = idx & 15;
        sB[t][j] = g_xdbl[(b * LL + l0 + t) * KX + 64 + j];
    }
    __syncthreads();

    float A0, Av[8];
    bool powok = load_A_half(A_log, d, half, A0, Av);
    powok = __all_sync(0xffffffffu, powok);   // warp-uniform path selection

    u64 h2[4];
#pragma unroll
    for (int q = 0; q < 4; q++) h2[q] = 0ull;
    float sdt = 0.f;

    const size_t base0 = (size_t)(b * LL + l0) * DD + d;
    const float* dtp = g_dt + base0;
    const float* up = u + base0;
    const float hm = half ? 1.f : 0.f;        // select e^8 multiplier branchlessly

    if (powok) {
        float dtc = __ldg(dtp), uc = __ldg(up);
#pragma unroll 2
        for (int t = 0; t < CH; t++) {
            float dtn = 0.f, un = 0.f;
            if (t < CH - 1) {
                dtn = __ldg(dtp + (size_t)(t + 1) * DD);
                un  = __ldg(up + (size_t)(t + 1) * DD);
            }
            sdt += dtc;
            float e1 = __expf(A0 * dtc);
            float e2 = e1 * e1;
            float e4 = e2 * e2;
            float e8 = e4 * e4;
            float m = fmaf(hm, e8 - 1.f, 1.f);   // half? e8 : 1
            u64 e44 = pk2(e4, e4);
            u64 aA = pk2(m * e1, m * e2);        // (e^{8h+1}, e^{8h+2})
            u64 aB = mul2(aA, pk2(e2, e2));      // (e^{8h+3}, e^{8h+4})
            float dtu = dtc * uc;
            u64 dtu2 = pk2(dtu, dtu);
            const int nb = half * 8;
            h2[0] = fma2(aA, h2[0], mul2(dtu2, *(const u64*)&sB[t][nb + 0]));
            h2[1] = fma2(aB, h2[1], mul2(dtu2, *(const u64*)&sB[t][nb + 2]));
            aA = mul2(aA, e44); aB = mul2(aB, e44);
            h2[2] = fma2(aA, h2[2], mul2(dtu2, *(const u64*)&sB[t][nb + 4]));
            h2[3] = fma2(aB, h2[3], mul2(dtu2, *(const u64*)&sB[t][nb + 6]));
            dtc = dtn; uc = un;
        }
    } else {
        for (int t = 0; t < CH; t++) {
            float dt = __ldg(dtp + (size_t)t * DD);
            float uu = __ldg(up + (size_t)t * DD);
            sdt += dt;
            float dtu = dt * uu;
            u64 dtu2 = pk2(dtu, dtu);
            const int nb = half * 8;
#pragma unroll
            for (int q = 0; q < 4; q++) {
                u64 a2 = pk2(__expf(dt * Av[2 * q]), __expf(dt * Av[2 * q + 1]));
                h2[q] = fma2(a2, h2[q], mul2(dtu2, *(const u64*)&sB[t][nb + 2 * q]));
            }
        }
    }

    const size_t cbase = ((size_t)((b * NCH + c) * DD) + d) * NN + half * 8;
    u64* hf = (u64*)(g_hf + cbase);
#pragma unroll
    for (int q = 0; q < 4; q++) hf[q] = h2[q];
    if (half == 0) g_sdt[(b * NCH + c) * DD + d] = sdt;
}

// ================= Scan phase B: inter-chunk recurrence (two-half preload) =================
__global__ void __launch_bounds__(256) k_scanB(const float* __restrict__ A_log) {
    const int gid = blockIdx.x * 256 + threadIdx.x;  // < B*D*N = 65536
    const int b = gid >> 15;
    const int rem = gid & 32767;
    const int d = rem >> 4;
    const int n = rem & 15;
    const float A = -__expf(A_log[d * 16 + n]);

    float h = 0.f;
#pragma unroll
    for (int half = 0; half < 2; half++) {
        float av[32], fv[32];
#pragma unroll
        for (int i = 0; i < 32; i++) {
            int base = (b * NCH + half * 32 + i) * DD + d;
            av[i] = g_sdt[base];
            fv[i] = g_hf[(size_t)base * NN + n];
        }
#pragma unroll
        for (int i = 0; i < 32; i++) av[i] = __expf(A * av[i]);
#pragma unroll
        for (int i = 0; i < 32; i++) {
            int base = (b * NCH + half * 32 + i) * DD + d;
            g_h0[(size_t)base * NN + n] = h;
            h = fmaf(av[i], h, fv[i]);
        }
    }
}

// ================= Scan phase C: n-split + shfl y-reduction =================
__global__ void __launch_bounds__(256) k_scanC(const float* __restrict__ u,
                                               const float* __restrict__ A_log,
                                               const float* __restrict__ Dv,
                                               float* __restrict__ out) {
    __shared__ __align__(16) float sBC[CH][32];
    const int b = blockIdx.z, c = blockIdx.y;
    const int tid = threadIdx.x;
    const int lane = tid & 31, wid = tid >> 5;
    const int half = lane >> 4;
    const int d = blockIdx.x * 128 + wid * 16 + (lane & 15);
    const int l0 = c * CH;

#pragma unroll
    for (int p = 0; p < 4; p++) {
        int idx = tid + p * 256;
        int t = idx >> 5, j = idx & 31;
        sBC[t][j] = g_xdbl[(b * LL + l0 + t) * KX + 64 + j];
    }
    __syncthreads();

    float A0, Av[8];
    bool powok = load_A_half(A_log, d, half, A0, Av);
    powok = __all_sync(0xffffffffu, powok);
    const float Dd = Dv[d];

    const size_t cbase = ((size_t)((b * NCH + c) * DD) + d) * NN + half * 8;
    u64 h2[4];
    {
        const u64* h0p = (const u64*)(g_h0 + cbase);
#pragma unroll
        for (int q = 0; q < 4; q++) h2[q] = h0p[q];
    }

    const size_t base0 = (size_t)(b * LL + l0) * DD + d;
    const float* dtp = g_dt + base0;
    const float* up = u + base0;
    float* yp = out + base0;
    const float hm = half ? 1.f : 0.f;

    if (powok) {
        float dtc = __ldg(dtp), uc = __ldg(up);
#pragma unroll 2
        for (int t = 0; t < CH; t++) {
            float dtn = 0.f, un = 0.f;
            if (t < CH - 1) {
                dtn = __ldg(dtp + (size_t)(t + 1) * DD);
                un  = __ldg(up + (size_t)(t + 1) * DD);
            }
            float e1 = __expf(A0 * dtc);
            float e2 = e1 * e1;
            float e4 = e2 * e2;
            float e8 = e4 * e4;
            float m = fmaf(hm, e8 - 1.f, 1.f);
            u64 e44 = pk2(e4, e4);
            u64 aA = pk2(m * e1, m * e2);
            u64 aB = mul2(aA, pk2(e2, e2));
            float dtu = dtc * uc;
            u64 dtu2 = pk2(dtu, dtu);
            const int nb = half * 8;
            u64 y2 = 0ull;
            h2[0] = fma2(aA, h2[0], mul2(dtu2, *(const u64*)&sBC[t][nb + 0]));
            h2[1] = fma2(aB, h2[1], mul2(dtu2, *(const u64*)&sBC[t][nb + 2]));
            y2 = fma2(h2[0], *(const u64*)&sBC[t][16 + nb + 0], y2);
            y2 = fma2(h2[1], *(const u64*)&sBC[t][16 + nb + 2], y2);
            aA = mul2(aA, e44); aB = mul2(aB, e44);
            h2[2] = fma2(aA, h2[2], mul2(dtu2, *(const u64*)&sBC[t][nb + 4]));
            h2[3] = fma2(aB, h2[3], mul2(dtu2, *(const u64*)&sBC[t][nb + 6]));
            y2 = fma2(h2[2], *(const u64*)&sBC[t][16 + nb + 4], y2);
            y2 = fma2(h2[3], *(const u64*)&sBC[t][16 + nb + 6], y2);
            float ylo, yhi; unpk2(y2, ylo, yhi);
            float ys = ylo + yhi;
            ys += __shfl_xor_sync(0xffffffffu, ys, 16);
            if (half == 0) yp[(size_t)t * DD] = fmaf(uc, Dd, ys);
            dtc = dtn; uc = un;
        }
    } else {
        for (int t = 0; t < CH; t++) {
            float dt = __ldg(dtp + (size_t)t * DD);
            float uu = __ldg(up + (size_t)t * DD);
            float dtu = dt * uu;
            u64 dtu2 = pk2(dtu, dtu);
            const int nb = half * 8;
            u64 y2 = 0ull;
#pragma unroll
            for (int q = 0; q < 4; q++) {
                u64 a2 = pk2(__expf(dt * Av[2 * q]), __expf(dt * Av[2 * q + 1]));
                h2[q] = fma2(a2, h2[q], mul2(dtu2, *(const u64*)&sBC[t][nb + 2 * q]));
                y2 = fma2(h2[q], *(const u64*)&sBC[t][16 + nb + 2 * q], y2);
            }
            float ylo, yhi; unpk2(y2, ylo, yhi);
            float ys = ylo + yhi;
            ys += __shfl_xor_sync(0xffffffffu, ys, 16);
            if (half == 0) yp[(size_t)t * DD] = fmaf(uu, Dd, ys);
        }
    }
}

// ================= launch =================
extern "C" void kernel_launch(void* const* d_in, const int* in_sizes, int n_in,
                              void* d_out, int out_size) {
    const float* u     = (const float*)d_in[0];
    const float* A_log = (const float*)d_in[1];
    const float* Dv    = (const float*)d_in[2];
    const float* Wx    = (const float*)d_in[3];
    const float* Wdt   = (const float*)d_in[4];
    const float* bdt   = (const float*)d_in[5];
    float* out = (float*)d_out;

    k_gemm1<<<dim3(32, 8), 256>>>(u, Wx);
    k_red1<<<384, 256>>>();
    k_gemm2<<<dim3(32, 16), 256>>>(Wdt, bdt);
    k_scanA<<<dim3(DD / 128, NCH, BB), 256>>>(u, A_log);
    k_scanB<<<(BB * DD * NN) / 256, 256>>>(A_log);
    k_scanC<<<dim3(DD / 128, NCH, BB), 256>>>(u, A_log, Dv, out);
}

// round 13
// speedup vs baseline: 1.0853x; 1.0853x over previous
#include <cuda_runtime.h>
#include <cuda_bf16.h>
#include <math.h>

// Problem constants
#define BB 2
#define LL 2048
#define DD 2048
#define NN 16
#define KX 96          // DT_RANK + 2*D_STATE
#define NCH 64         // chunks along L
#define CH 32          // chunk length (NCH*CH == LL)
#define KSPL 16        // gemm1 K-split

typedef unsigned long long u64;

// ---------------- scratch (device globals) ----------------
__device__ __align__(16) float g_xpart[KSPL][BB * LL * KX];  // gemm1 K-split partials
__device__ __align__(16) float g_xdbl[BB * LL * KX];
__device__ __align__(16) float g_dt[BB * LL * DD];
__device__ __align__(16) float g_hf[BB * NCH * DD * NN];
__device__ __align__(16) float g_h0[BB * NCH * DD * NN];
__device__ __align__(16) float g_sdt[BB * NCH * DD];

// ---------------- f32x2 helpers ----------------
__device__ __forceinline__ u64 pk2(float lo, float hi) {
    u64 r; asm("mov.b64 %0,{%1,%2};" : "=l"(r) : "f"(lo), "f"(hi)); return r;
}
__device__ __forceinline__ void unpk2(u64 v, float& lo, float& hi) {
    asm("mov.b64 {%0,%1},%2;" : "=f"(lo), "=f"(hi) : "l"(v));
}
__device__ __forceinline__ u64 fma2(u64 a, u64 b, u64 c) {
    u64 d; asm("fma.rn.f32x2 %0,%1,%2,%3;" : "=l"(d) : "l"(a), "l"(b), "l"(c)); return d;
}
__device__ __forceinline__ u64 mul2(u64 a, u64 b) {
    u64 d; asm("mul.rn.f32x2 %0,%1,%2;" : "=l"(d) : "l"(a), "l"(b)); return d;
}

// ================= GEMM1 (K-split x16): 128-row tiles, micro 4rp x 6c, double-buffered, k-tile 16 =================
__global__ void __launch_bounds__(256) k_gemm1(const float* __restrict__ u,
                                               const float* __restrict__ Wx) {
    __shared__ __align__(16) u64 us2[2][16][65];
    __shared__ __align__(16) u64 ws2[2][16][97];
    const int r0 = blockIdx.x * 128;
    const int kbeg = blockIdx.y * 128;          // K-slice of 128
    const int tid = threadIdx.x;
    const int tx = tid & 15, ty = tid >> 4;

    u64 acc[4][6];
#pragma unroll
    for (int i = 0; i < 4; i++)
#pragma unroll
        for (int j = 0; j < 6; j++) acc[i][j] = 0ull;

    auto stage = [&](int k0, int buf) {
        {
            int rp = tid >> 2;
            int kq = (tid & 3) * 4;
            const float4 a0 = *(const float4*)&u[(size_t)(r0 + 2 * rp) * 2048 + k0 + kq];
            const float4 a1 = *(const float4*)&u[(size_t)(r0 + 2 * rp + 1) * 2048 + k0 + kq];
            us2[buf][kq + 0][rp] = pk2(a0.x, a1.x);
            us2[buf][kq + 1][rp] = pk2(a0.y, a1.y);
            us2[buf][kq + 2][rp] = pk2(a0.z, a1.z);
            us2[buf][kq + 3][rp] = pk2(a0.w, a1.w);
        }
#pragma unroll
        for (int p = 0; p < 2; p++) {
            int g = tid + p * 256;
            if (g < 384) {
                int c = g >> 2;
                int kw = (g & 3) * 4;
                float4 w = *(const float4*)&Wx[(size_t)c * 2048 + k0 + kw];
                ws2[buf][kw + 0][c] = pk2(w.x, w.x);
                ws2[buf][kw + 1][c] = pk2(w.y, w.y);
                ws2[buf][kw + 2][c] = pk2(w.z, w.z);
                ws2[buf][kw + 3][c] = pk2(w.w, w.w);
            }
        }
    };

    stage(kbeg, 0);
    __syncthreads();
#pragma unroll
    for (int kt = 0; kt < 8; kt++) {
        if (kt < 7) stage(kbeg + (kt + 1) * 16, (kt + 1) & 1);
        const int buf = kt & 1;
#pragma unroll
        for (int k = 0; k < 16; k++) {
            u64 ua[4];
#pragma unroll
            for (int i = 0; i < 4; i++) ua[i] = us2[buf][k][ty * 4 + i];
#pragma unroll
            for (int j = 0; j < 6; j++) {
                u64 w2 = ws2[buf][k][tx * 6 + j];
#pragma unroll
                for (int i = 0; i < 4; i++) acc[i][j] = fma2(ua[i], w2, acc[i][j]);
            }
        }
        __syncthreads();
    }
    float* dst = g_xpart[blockIdx.y];
#pragma unroll
    for (int i = 0; i < 4; i++)
#pragma unroll
        for (int j = 0; j < 6; j++) {
            float lo, hi; unpk2(acc[i][j], lo, hi);
            int row = r0 + ty * 8 + 2 * i;
            int col = tx * 6 + j;
            dst[row * KX + col] = lo;
            dst[(row + 1) * KX + col] = hi;
        }
}

// ================= reduce the 16 partials (deterministic) =================
__global__ void __launch_bounds__(256) k_red1() {
    int idx = blockIdx.x * 256 + threadIdx.x;
    float4 s = ((const float4*)g_xpart[0])[idx];
#pragma unroll
    for (int p = 1; p < KSPL; p++) {
        float4 a = ((const float4*)g_xpart[p])[idx];
        s.x += a.x; s.y += a.y; s.z += a.z; s.w += a.w;
    }
    ((float4*)g_xdbl)[idx] = s;
}

// ========= GEMM2: 128x128 tile, micro 4rp x 8c =========
__global__ void __launch_bounds__(256) k_gemm2(const float* __restrict__ Wdt,
                                               const float* __restrict__ bdt) {
    __shared__ __align__(16) u64   us2[64][65];
    __shared__ __align__(16) float ws[64][128];
    const int r0 = blockIdx.x * 128;
    const int c0 = blockIdx.y * 128;
    const int tid = threadIdx.x;
    const int tx = tid & 15, ty = tid >> 4;

#pragma unroll
    for (int p = 0; p < 4; p++) {
        int g = tid + p * 256;
        int rp = g >> 4;
        int kq = (g & 15) * 4;
        const float4 a0 = *(const float4*)&g_xdbl[(r0 + 2 * rp) * KX + kq];
        const float4 a1 = *(const float4*)&g_xdbl[(r0 + 2 * rp + 1) * KX + kq];
        us2[kq + 0][rp] = pk2(a0.x, a1.x);
        us2[kq + 1][rp] = pk2(a0.y, a1.y);
        us2[kq + 2][rp] = pk2(a0.z, a1.z);
        us2[kq + 3][rp] = pk2(a0.w, a1.w);
    }
#pragma unroll
    for (int p = 0; p < 8; p++) {
        int g = tid + p * 256;
        int c = g & 127;
        int kq = (g >> 7) * 4;
        float4 w = *(const float4*)&Wdt[(size_t)(c0 + c) * 64 + kq];
        ws[kq + 0][c] = w.x;
        ws[kq + 1][c] = w.y;
        ws[kq + 2][c] = w.z;
        ws[kq + 3][c] = w.w;
    }
    __syncthreads();

    u64 acc[4][8];
#pragma unroll
    for (int i = 0; i < 4; i++)
#pragma unroll
        for (int j = 0; j < 8; j++) acc[i][j] = 0ull;

#pragma unroll 8
    for (int k = 0; k < 64; k++) {
        u64 ua[4];
#pragma unroll
        for (int i = 0; i < 4; i++) ua[i] = us2[k][ty * 4 + i];
        float4 wa = *(const float4*)&ws[k][tx * 8];
        float4 wb = *(const float4*)&ws[k][tx * 8 + 4];
        u64 w2[8] = {pk2(wa.x, wa.x), pk2(wa.y, wa.y), pk2(wa.z, wa.z), pk2(wa.w, wa.w),
                     pk2(wb.x, wb.x), pk2(wb.y, wb.y), pk2(wb.z, wb.z), pk2(wb.w, wb.w)};
#pragma unroll
        for (int j = 0; j < 8; j++)
#pragma unroll
            for (int i = 0; i < 4; i++) acc[i][j] = fma2(ua[i], w2[j], acc[i][j]);
    }

    float bb[8];
#pragma unroll
    for (int j = 0; j < 8; j++) bb[j] = bdt[c0 + tx * 8 + j];

#pragma unroll
    for (int i = 0; i < 4; i++)
#pragma unroll
        for (int j = 0; j < 8; j++) {
            float lo, hi; unpk2(acc[i][j], lo, hi);
            int row = r0 + ty * 8 + 2 * i;
            int col = c0 + tx * 8 + j;
            float x0 = lo + bb[j];
            float x1 = hi + bb[j];
            float s0 = fmaxf(x0, 0.f) + __logf(1.f + __expf(-fabsf(x0)));
            float s1 = fmaxf(x1, 0.f) + __logf(1.f + __expf(-fabsf(x1)));
            g_dt[(size_t)row * DD + col] = s0;
            g_dt[(size_t)(row + 1) * DD + col] = s1;
        }
}

// ---------------- per-thread A setup + structure check (float4 loads) ----------------
__device__ __forceinline__ bool load_A(const float* __restrict__ A_log, int d, float Av[16]) {
#pragma unroll
    for (int n = 0; n < 16; n += 4) {
        float4 a4 = *(const float4*)&A_log[d * 16 + n];
        Av[n]     = -__expf(a4.x);
        Av[n + 1] = -__expf(a4.y);
        Av[n + 2] = -__expf(a4.z);
        Av[n + 3] = -__expf(a4.w);
    }
    bool ok = (Av[0] < 0.f);
#pragma unroll
    for (int n = 1; n < 16; n++) {
        float tgt = (float)(n + 1) * Av[0];
        ok = ok && (fabsf(Av[n] - tgt) <= 4e-6f * fabsf(tgt));
    }
    return ok;
}

// ================= Scan phase A: local scan per chunk from h=0 (round-11 best) =================
__global__ void __launch_bounds__(256) k_scanA(const float* __restrict__ u,
                                               const float* __restrict__ A_log) {
    __shared__ __align__(16) float sB[CH][16];
    const int b = blockIdx.z, c = blockIdx.y;
    const int tid = threadIdx.x;
    const int d = blockIdx.x * 256 + tid;
    const int l0 = c * CH;

#pragma unroll
    for (int p = 0; p < 2; p++) {
        int idx = tid + p * 256;
        int t = idx >> 4, j = idx & 15;
        sB[t][j] = g_xdbl[(b * LL + l0 + t) * KX + 64 + j];
    }
    __syncthreads();

    float Av[16];
    const bool powok = load_A(A_log, d, Av);

    u64 h2[8];
#pragma unroll
    for (int p = 0; p < 8; p++) h2[p] = 0ull;
    float sdt = 0.f;

    const size_t base0 = (size_t)(b * LL + l0) * DD + d;
    const float* dtp = g_dt + base0;
    const float* up = u + base0;

    if (powok) {
        const float A0 = Av[0];
        float dtc = __ldg(dtp), uc = __ldg(up);
#pragma unroll 2
        for (int t = 0; t < CH; t++) {
            float dtn = 0.f, un = 0.f;
            if (t < CH - 1) {
                dtn = __ldg(dtp + (size_t)(t + 1) * DD);
                un  = __ldg(up + (size_t)(t + 1) * DD);
            }
            sdt += dtc;
            float e1 = __expf(A0 * dtc);
            float e2 = e1 * e1;
            float e4 = e2 * e2;
            u64 e44 = pk2(e4, e4);
            u64 aA = pk2(e1, e2);          // (e^1, e^2)
            u64 aB = mul2(aA, pk2(e2, e2)); // (e^3, e^4)
            float dtu = dtc * uc;
            u64 dtu2 = pk2(dtu, dtu);
#pragma unroll
            for (int p = 0; p < 8; p += 2) {
                u64 B2a = *(const u64*)&sB[t][2 * p];
                u64 B2b = *(const u64*)&sB[t][2 * p + 2];
                h2[p]     = fma2(aA, h2[p],     mul2(dtu2, B2a));
                h2[p + 1] = fma2(aB, h2[p + 1], mul2(dtu2, B2b));
                if (p < 6) { aA = mul2(aA, e44); aB = mul2(aB, e44); }
            }
            dtc = dtn; uc = un;
        }
    } else {
        for (int t = 0; t < CH; t++) {
            float dt = __ldg(dtp + (size_t)t * DD);
            float uu = __ldg(up + (size_t)t * DD);
            sdt += dt;
            float dtu = dt * uu;
            u64 dtu2 = pk2(dtu, dtu);
#pragma unroll
            for (int p = 0; p < 8; p++) {
                u64 a2 = pk2(__expf(dt * Av[2 * p]), __expf(dt * Av[2 * p + 1]));
                u64 B2 = *(const u64*)&sB[t][2 * p];
                h2[p] = fma2(a2, h2[p], mul2(dtu2, B2));
            }
        }
    }

    u64* hf = (u64*)(g_hf + ((size_t)((b * NCH + c) * DD) + d) * NN);
#pragma unroll
    for (int p = 0; p < 8; p++) hf[p] = h2[p];
    g_sdt[(b * NCH + c) * DD + d] = sdt;
}

// ================= Scan phase B: inter-chunk recurrence (two-half preload) =================
__global__ void __launch_bounds__(256) k_scanB(const float* __restrict__ A_log) {
    const int gid = blockIdx.x * 256 + threadIdx.x;  // < B*D*N = 65536
    const int b = gid >> 15;
    const int rem = gid & 32767;
    const int d = rem >> 4;
    const int n = rem & 15;
    const float A = -__expf(A_log[d * 16 + n]);

    float h = 0.f;
#pragma unroll
    for (int half = 0; half < 2; half++) {
        float av[32], fv[32];
#pragma unroll
        for (int i = 0; i < 32; i++) {
            int base = (b * NCH + half * 32 + i) * DD + d;
            av[i] = g_sdt[base];
            fv[i] = g_hf[(size_t)base * NN + n];
        }
#pragma unroll
        for (int i = 0; i < 32; i++) av[i] = __expf(A * av[i]);
#pragma unroll
        for (int i = 0; i < 32; i++) {
            int base = (b * NCH + half * 32 + i) * DD + d;
            g_h0[(size_t)base * NN + n] = h;
            h = fmaf(av[i], h, fv[i]);
        }
    }
}

// ================= Scan phase C: re-scan with correct h0, emit y (round-11 best) =================
__global__ void __launch_bounds__(256) k_scanC(const float* __restrict__ u,
                                               const float* __restrict__ A_log,
                                               const float* __restrict__ Dv,
                                               float* __restrict__ out) {
    __shared__ __align__(16) float sBC[CH][32];
    const int b = blockIdx.z, c = blockIdx.y;
    const int tid = threadIdx.x;
    const int d = blockIdx.x * 256 + tid;
    const int l0 = c * CH;

#pragma unroll
    for (int p = 0; p < 4; p++) {
        int idx = tid + p * 256;
        int t = idx >> 5, j = idx & 31;
        sBC[t][j] = g_xdbl[(b * LL + l0 + t) * KX + 64 + j];
    }
    __syncthreads();

    float Av[16];
    const bool powok = load_A(A_log, d, Av);
    const float Dd = Dv[d];

    u64 h2[8];
    {
        const u64* h0p = (const u64*)(g_h0 + ((size_t)((b * NCH + c) * DD) + d) * NN);
#pragma unroll
        for (int p = 0; p < 8; p++) h2[p] = h0p[p];
    }

    const size_t base0 = (size_t)(b * LL + l0) * DD + d;
    const float* dtp = g_dt + base0;
    const float* up = u + base0;
    float* yp = out + base0;

    if (powok) {
        const float A0 = Av[0];
        float dtc = __ldg(dtp), uc = __ldg(up);
#pragma unroll 2
        for (int t = 0; t < CH; t++) {
            float dtn = 0.f, un = 0.f;
            if (t < CH - 1) {
                dtn = __ldg(dtp + (size_t)(t + 1) * DD);
                un  = __ldg(up + (size_t)(t + 1) * DD);
            }
            float e1 = __expf(A0 * dtc);
            float e2 = e1 * e1;
            float e4 = e2 * e2;
            u64 e44 = pk2(e4, e4);
            u64 aA = pk2(e1, e2);
            u64 aB = mul2(aA, pk2(e2, e2));
            float dtu = dtc * uc;
            u64 dtu2 = pk2(dtu, dtu);
            u64 y2 = 0ull;
#pragma unroll
            for (int p = 0; p < 8; p += 2) {
                u64 B2a = *(const u64*)&sBC[t][2 * p];
                u64 B2b = *(const u64*)&sBC[t][2 * p + 2];
                u64 C2a = *(const u64*)&sBC[t][16 + 2 * p];
                u64 C2b = *(const u64*)&sBC[t][16 + 2 * p + 2];
                h2[p]     = fma2(aA, h2[p],     mul2(dtu2, B2a));
                h2[p + 1] = fma2(aB, h2[p + 1], mul2(dtu2, B2b));
                y2 = fma2(h2[p], C2a, y2);
                y2 = fma2(h2[p + 1], C2b, y2);
                if (p < 6) { aA = mul2(aA, e44); aB = mul2(aB, e44); }
            }
            float ylo, yhi; unpk2(y2, ylo, yhi);
            yp[(size_t)t * DD] = fmaf(uc, Dd, ylo + yhi);
            dtc = dtn; uc = un;
        }
    } else {
        for (int t = 0; t < CH; t++) {
            float dt = __ldg(dtp + (size_t)t * DD);
            float uu = __ldg(up + (size_t)t * DD);
            float dtu = dt * uu;
            u64 dtu2 = pk2(dtu, dtu);
            u64 y2 = 0ull;
#pragma unroll
            for (int p = 0; p < 8; p++) {
                u64 a2 = pk2(__expf(dt * Av[2 * p]), __expf(dt * Av[2 * p + 1]));
                u64 B2 = *(const u64*)&sBC[t][2 * p];
                u64 C2 = *(const u64*)&sBC[t][16 + 2 * p];
                h2[p] = fma2(a2, h2[p], mul2(dtu2, B2));
                y2 = fma2(h2[p], C2, y2);
            }
            float ylo, yhi; unpk2(y2, ylo, yhi);
            yp[(size_t)t * DD] = fmaf(uu, Dd, ylo + yhi);
        }
    }
}

// ================= launch =================
extern "C" void kernel_launch(void* const* d_in, const int* in_sizes, int n_in,
                              void* d_out, int out_size) {
    const float* u     = (const float*)d_in[0];
    const float* A_log = (const float*)d_in[1];
    const float* Dv    = (const float*)d_in[2];
    const float* Wx    = (const float*)d_in[3];
    const float* Wdt   = (const float*)d_in[4];
    const float* bdt   = (const float*)d_in[5];
    float* out = (float*)d_out;

    k_gemm1<<<dim3(32, KSPL), 256>>>(u, Wx);
    k_red1<<<384, 256>>>();
    k_gemm2<<<dim3(32, 16), 256>>>(Wdt, bdt);
    k_scanA<<<dim3(DD / 256, NCH, BB), 256>>>(u, A_log);
    k_scanB<<<(BB * DD * NN) / 256, 256>>>(A_log);
    k_scanC<<<dim3(DD / 256, NCH, BB), 256>>>(u, A_log, Dv, out);
}

// round 14
// speedup vs baseline: 1.0977x; 1.0114x over previous
#include <cuda_runtime.h>
#include <cuda_bf16.h>
#include <math.h>

// Problem constants
#define BB 2
#define LL 2048
#define DD 2048
#define NN 16
#define KX 96          // DT_RANK + 2*D_STATE
#define NCH 64         // chunks along L
#define CH 32          // chunk length (NCH*CH == LL)
#define KSPL 8         // gemm1 K-split

typedef unsigned long long u64;

// ---------------- scratch (device globals) ----------------
__device__ __align__(16) float g_xpart[KSPL][BB * LL * KX];  // gemm1 K-split partials
__device__ __align__(16) float g_xdbl[BB * LL * KX];
__device__ __align__(16) float g_dt[BB * LL * DD];
__device__ __align__(16) float g_hf[BB * NCH * DD * NN];
__device__ __align__(16) float g_h0[BB * NCH * DD * NN];
__device__ __align__(16) float g_sdt[BB * NCH * DD];
__device__ unsigned int g_cnt[32];   // zero-init; reset by the reducing block each launch

// ---------------- f32x2 helpers ----------------
__device__ __forceinline__ u64 pk2(float lo, float hi) {
    u64 r; asm("mov.b64 %0,{%1,%2};" : "=l"(r) : "f"(lo), "f"(hi)); return r;
}
__device__ __forceinline__ void unpk2(u64 v, float& lo, float& hi) {
    asm("mov.b64 {%0,%1},%2;" : "=f"(lo), "=f"(hi) : "l"(v));
}
__device__ __forceinline__ u64 fma2(u64 a, u64 b, u64 c) {
    u64 d; asm("fma.rn.f32x2 %0,%1,%2,%3;" : "=l"(d) : "l"(a), "l"(b), "l"(c)); return d;
}
__device__ __forceinline__ u64 mul2(u64 a, u64 b) {
    u64 d; asm("mul.rn.f32x2 %0,%1,%2;" : "=l"(d) : "l"(a), "l"(b)); return d;
}

// ================= GEMM1 (K-split x8): 128-row tiles, micro 4rp x 6c, double-buffered,
//                   k-tile 16, FUSED last-block reduction =================
__global__ void __launch_bounds__(256) k_gemm1(const float* __restrict__ u,
                                               const float* __restrict__ Wx) {
    __shared__ __align__(16) u64 us2[2][16][65];
    __shared__ __align__(16) u64 ws2[2][16][97];
    __shared__ bool s_last;
    const int r0 = blockIdx.x * 128;
    const int kbeg = blockIdx.y * 256;
    const int tid = threadIdx.x;
    const int tx = tid & 15, ty = tid >> 4;

    u64 acc[4][6];
#pragma unroll
    for (int i = 0; i < 4; i++)
#pragma unroll
        for (int j = 0; j < 6; j++) acc[i][j] = 0ull;

    auto stage = [&](int k0, int buf) {
        {
            int rp = tid >> 2;
            int kq = (tid & 3) * 4;
            const float4 a0 = *(const float4*)&u[(size_t)(r0 + 2 * rp) * 2048 + k0 + kq];
            const float4 a1 = *(const float4*)&u[(size_t)(r0 + 2 * rp + 1) * 2048 + k0 + kq];
            us2[buf][kq + 0][rp] = pk2(a0.x, a1.x);
            us2[buf][kq + 1][rp] = pk2(a0.y, a1.y);
            us2[buf][kq + 2][rp] = pk2(a0.z, a1.z);
            us2[buf][kq + 3][rp] = pk2(a0.w, a1.w);
        }
#pragma unroll
        for (int p = 0; p < 2; p++) {
            int g = tid + p * 256;
            if (g < 384) {
                int c = g >> 2;
                int kw = (g & 3) * 4;
                float4 w = *(const float4*)&Wx[(size_t)c * 2048 + k0 + kw];
                ws2[buf][kw + 0][c] = pk2(w.x, w.x);
                ws2[buf][kw + 1][c] = pk2(w.y, w.y);
                ws2[buf][kw + 2][c] = pk2(w.z, w.z);
                ws2[buf][kw + 3][c] = pk2(w.w, w.w);
            }
        }
    };

    stage(kbeg, 0);
    __syncthreads();
#pragma unroll
    for (int kt = 0; kt < 16; kt++) {
        if (kt < 15) stage(kbeg + (kt + 1) * 16, (kt + 1) & 1);
        const int buf = kt & 1;
#pragma unroll
        for (int k = 0; k < 16; k++) {
            u64 ua[4];
#pragma unroll
            for (int i = 0; i < 4; i++) ua[i] = us2[buf][k][ty * 4 + i];
#pragma unroll
            for (int j = 0; j < 6; j++) {
                u64 w2 = ws2[buf][k][tx * 6 + j];
#pragma unroll
                for (int i = 0; i < 4; i++) acc[i][j] = fma2(ua[i], w2, acc[i][j]);
            }
        }
        __syncthreads();
    }
    float* dst = g_xpart[blockIdx.y];
#pragma unroll
    for (int i = 0; i < 4; i++)
#pragma unroll
        for (int j = 0; j < 6; j++) {
            float lo, hi; unpk2(acc[i][j], lo, hi);
            int row = r0 + ty * 8 + 2 * i;
            int col = tx * 6 + j;
            dst[row * KX + col] = lo;
            dst[(row + 1) * KX + col] = hi;
        }

    // -------- fused reduction: 8th arriving block for this row-tile sums partials --------
    __threadfence();                               // make partial stores visible chip-wide
    if (tid == 0) {
        unsigned int old = atomicAdd(&g_cnt[blockIdx.x], 1u);
        s_last = (old == KSPL - 1);
    }
    __syncthreads();
    if (s_last) {
        __threadfence();                           // acquire side: order reads after the count
        const int base4 = r0 * (KX / 4);           // float4 index of this tile's region
        for (int i = tid; i < 128 * (KX / 4); i += 256) {
            float4 s = ((const float4*)g_xpart[0])[base4 + i];
#pragma unroll
            for (int p = 1; p < KSPL; p++) {
                float4 a = ((const float4*)g_xpart[p])[base4 + i];
                s.x += a.x; s.y += a.y; s.z += a.z; s.w += a.w;
            }
            ((float4*)g_xdbl)[base4 + i] = s;
        }
        if (tid == 0) g_cnt[blockIdx.x] = 0;       // reset for next graph replay
    }
}

// ========= GEMM2: 128x128 tile, micro 4rp x 8c =========
__global__ void __launch_bounds__(256) k_gemm2(const float* __restrict__ Wdt,
                                               const float* __restrict__ bdt) {
    __shared__ __align__(16) u64   us2[64][65];
    __shared__ __align__(16) float ws[64][128];
    const int r0 = blockIdx.x * 128;
    const int c0 = blockIdx.y * 128;
    const int tid = threadIdx.x;
    const int tx = tid & 15, ty = tid >> 4;

#pragma unroll
    for (int p = 0; p < 4; p++) {
        int g = tid + p * 256;
        int rp = g >> 4;
        int kq = (g & 15) * 4;
        const float4 a0 = *(const float4*)&g_xdbl[(r0 + 2 * rp) * KX + kq];
        const float4 a1 = *(const float4*)&g_xdbl[(r0 + 2 * rp + 1) * KX + kq];
        us2[kq + 0][rp] = pk2(a0.x, a1.x);
        us2[kq + 1][rp] = pk2(a0.y, a1.y);
        us2[kq + 2][rp] = pk2(a0.z, a1.z);
        us2[kq + 3][rp] = pk2(a0.w, a1.w);
    }
#pragma unroll
    for (int p = 0; p < 8; p++) {
        int g = tid + p * 256;
        int c = g & 127;
        int kq = (g >> 7) * 4;
        float4 w = *(const float4*)&Wdt[(size_t)(c0 + c) * 64 + kq];
        ws[kq + 0][c] = w.x;
        ws[kq + 1][c] = w.y;
        ws[kq + 2][c] = w.z;
        ws[kq + 3][c] = w.w;
    }
    __syncthreads();

    u64 acc[4][8];
#pragma unroll
    for (int i = 0; i < 4; i++)
#pragma unroll
        for (int j = 0; j < 8; j++) acc[i][j] = 0ull;

#pragma unroll 8
    for (int k = 0; k < 64; k++) {
        u64 ua[4];
#pragma unroll
        for (int i = 0; i < 4; i++) ua[i] = us2[k][ty * 4 + i];
        float4 wa = *(const float4*)&ws[k][tx * 8];
        float4 wb = *(const float4*)&ws[k][tx * 8 + 4];
        u64 w2[8] = {pk2(wa.x, wa.x), pk2(wa.y, wa.y), pk2(wa.z, wa.z), pk2(wa.w, wa.w),
                     pk2(wb.x, wb.x), pk2(wb.y, wb.y), pk2(wb.z, wb.z), pk2(wb.w, wb.w)};
#pragma unroll
        for (int j = 0; j < 8; j++)
#pragma unroll
            for (int i = 0; i < 4; i++) acc[i][j] = fma2(ua[i], w2[j], acc[i][j]);
    }

    float bb[8];
#pragma unroll
    for (int j = 0; j < 8; j++) bb[j] = bdt[c0 + tx * 8 + j];

#pragma unroll
    for (int i = 0; i < 4; i++)
#pragma unroll
        for (int j = 0; j < 8; j++) {
            float lo, hi; unpk2(acc[i][j], lo, hi);
            int row = r0 + ty * 8 + 2 * i;
            int col = c0 + tx * 8 + j;
            float x0 = lo + bb[j];
            float x1 = hi + bb[j];
            float s0 = fmaxf(x0, 0.f) + __logf(1.f + __expf(-fabsf(x0)));
            float s1 = fmaxf(x1, 0.f) + __logf(1.f + __expf(-fabsf(x1)));
            g_dt[(size_t)row * DD + col] = s0;
            g_dt[(size_t)(row + 1) * DD + col] = s1;
        }
}

// ---------------- per-thread A setup + structure check (float4 loads) ----------------
__device__ __forceinline__ bool load_A(const float* __restrict__ A_log, int d, float Av[16]) {
#pragma unroll
    for (int n = 0; n < 16; n += 4) {
        float4 a4 = *(const float4*)&A_log[d * 16 + n];
        Av[n]     = -__expf(a4.x);
        Av[n + 1] = -__expf(a4.y);
        Av[n + 2] = -__expf(a4.z);
        Av[n + 3] = -__expf(a4.w);
    }
    bool ok = (Av[0] < 0.f);
#pragma unroll
    for (int n = 1; n < 16; n++) {
        float tgt = (float)(n + 1) * Av[0];
        ok = ok && (fabsf(Av[n] - tgt) <= 4e-6f * fabsf(tgt));
    }
    return ok;
}

// ================= Scan phase A: local scan per chunk from h=0 (round-11 best) =================
__global__ void __launch_bounds__(256) k_scanA(const float* __restrict__ u,
                                               const float* __restrict__ A_log) {
    __shared__ __align__(16) float sB[CH][16];
    const int b = blockIdx.z, c = blockIdx.y;
    const int tid = threadIdx.x;
    const int d = blockIdx.x * 256 + tid;
    const int l0 = c * CH;

#pragma unroll
    for (int p = 0; p < 2; p++) {
        int idx = tid + p * 256;
        int t = idx >> 4, j = idx & 15;
        sB[t][j] = g_xdbl[(b * LL + l0 + t) * KX + 64 + j];
    }
    __syncthreads();

    float Av[16];
    const bool powok = load_A(A_log, d, Av);

    u64 h2[8];
#pragma unroll
    for (int p = 0; p < 8; p++) h2[p] = 0ull;
    float sdt = 0.f;

    const size_t base0 = (size_t)(b * LL + l0) * DD + d;
    const float* dtp = g_dt + base0;
    const float* up = u + base0;

    if (powok) {
        const float A0 = Av[0];
        float dtc = __ldg(dtp), uc = __ldg(up);
#pragma unroll 2
        for (int t = 0; t < CH; t++) {
            float dtn = 0.f, un = 0.f;
            if (t < CH - 1) {
                dtn = __ldg(dtp + (size_t)(t + 1) * DD);
                un  = __ldg(up + (size_t)(t + 1) * DD);
            }
            sdt += dtc;
            float e1 = __expf(A0 * dtc);
            float e2 = e1 * e1;
            float e4 = e2 * e2;
            u64 e44 = pk2(e4, e4);
            u64 aA = pk2(e1, e2);          // (e^1, e^2)
            u64 aB = mul2(aA, pk2(e2, e2)); // (e^3, e^4)
            float dtu = dtc * uc;
            u64 dtu2 = pk2(dtu, dtu);
#pragma unroll
            for (int p = 0; p < 8; p += 2) {
                u64 B2a = *(const u64*)&sB[t][2 * p];
                u64 B2b = *(const u64*)&sB[t][2 * p + 2];
                h2[p]     = fma2(aA, h2[p],     mul2(dtu2, B2a));
                h2[p + 1] = fma2(aB, h2[p + 1], mul2(dtu2, B2b));
                if (p < 6) { aA = mul2(aA, e44); aB = mul2(aB, e44); }
            }
            dtc = dtn; uc = un;
        }
    } else {
        for (int t = 0; t < CH; t++) {
            float dt = __ldg(dtp + (size_t)t * DD);
            float uu = __ldg(up + (size_t)t * DD);
            sdt += dt;
            float dtu = dt * uu;
            u64 dtu2 = pk2(dtu, dtu);
#pragma unroll
            for (int p = 0; p < 8; p++) {
                u64 a2 = pk2(__expf(dt * Av[2 * p]), __expf(dt * Av[2 * p + 1]));
                u64 B2 = *(const u64*)&sB[t][2 * p];
                h2[p] = fma2(a2, h2[p], mul2(dtu2, B2));
            }
        }
    }

    u64* hf = (u64*)(g_hf + ((size_t)((b * NCH + c) * DD) + d) * NN);
#pragma unroll
    for (int p = 0; p < 8; p++) hf[p] = h2[p];
    g_sdt[(b * NCH + c) * DD + d] = sdt;
}

// ================= Scan phase B: inter-chunk recurrence (two-half preload) =================
__global__ void __launch_bounds__(256) k_scanB(const float* __restrict__ A_log) {
    const int gid = blockIdx.x * 256 + threadIdx.x;  // < B*D*N = 65536
    const int b = gid >> 15;
    const int rem = gid & 32767;
    const int d = rem >> 4;
    const int n = rem & 15;
    const float A = -__expf(A_log[d * 16 + n]);

    float h = 0.f;
#pragma unroll
    for (int half = 0; half < 2; half++) {
        float av[32], fv[32];
#pragma unroll
        for (int i = 0; i < 32; i++) {
            int base = (b * NCH + half * 32 + i) * DD + d;
            av[i] = g_sdt[base];
            fv[i] = g_hf[(size_t)base * NN + n];
        }
#pragma unroll
        for (int i = 0; i < 32; i++) av[i] = __expf(A * av[i]);
#pragma unroll
        for (int i = 0; i < 32; i++) {
            int base = (b * NCH + half * 32 + i) * DD + d;
            g_h0[(size_t)base * NN + n] = h;
            h = fmaf(av[i], h, fv[i]);
        }
    }
}

// ================= Scan phase C: re-scan with correct h0, emit y (round-11 best) =================
__global__ void __launch_bounds__(256) k_scanC(const float* __restrict__ u,
                                               const float* __restrict__ A_log,
                                               const float* __restrict__ Dv,
                                               float* __restrict__ out) {
    __shared__ __align__(16) float sBC[CH][32];
    const int b = blockIdx.z, c = blockIdx.y;
    const int tid = threadIdx.x;
    const int d = blockIdx.x * 256 + tid;
    const int l0 = c * CH;

#pragma unroll
    for (int p = 0; p < 4; p++) {
        int idx = tid + p * 256;
        int t = idx >> 5, j = idx & 31;
        sBC[t][j] = g_xdbl[(b * LL + l0 + t) * KX + 64 + j];
    }
    __syncthreads();

    float Av[16];
    const bool powok = load_A(A_log, d, Av);
    const float Dd = Dv[d];

    u64 h2[8];
    {
        const u64* h0p = (const u64*)(g_h0 + ((size_t)((b * NCH + c) * DD) + d) * NN);
#pragma unroll
        for (int p = 0; p < 8; p++) h2[p] = h0p[p];
    }

    const size_t base0 = (size_t)(b * LL + l0) * DD + d;
    const float* dtp = g_dt + base0;
    const float* up = u + base0;
    float* yp = out + base0;

    if (powok) {
        const float A0 = Av[0];
        float dtc = __ldg(dtp), uc = __ldg(up);
#pragma unroll 2
        for (int t = 0; t < CH; t++) {
            float dtn = 0.f, un = 0.f;
            if (t < CH - 1) {
                dtn = __ldg(dtp + (size_t)(t + 1) * DD);
                un  = __ldg(up + (size_t)(t + 1) * DD);
            }
            float e1 = __expf(A0 * dtc);
            float e2 = e1 * e1;
            float e4 = e2 * e2;
            u64 e44 = pk2(e4, e4);
            u64 aA = pk2(e1, e2);
            u64 aB = mul2(aA, pk2(e2, e2));
            float dtu = dtc * uc;
            u64 dtu2 = pk2(dtu, dtu);
            u64 y2 = 0ull;
#pragma unroll
            for (int p = 0; p < 8; p += 2) {
                u64 B2a = *(const u64*)&sBC[t][2 * p];
                u64 B2b = *(const u64*)&sBC[t][2 * p + 2];
                u64 C2a = *(const u64*)&sBC[t][16 + 2 * p];
                u64 C2b = *(const u64*)&sBC[t][16 + 2 * p + 2];
                h2[p]     = fma2(aA, h2[p],     mul2(dtu2, B2a));
                h2[p + 1] = fma2(aB, h2[p + 1], mul2(dtu2, B2b));
                y2 = fma2(h2[p], C2a, y2);
                y2 = fma2(h2[p + 1], C2b, y2);
                if (p < 6) { aA = mul2(aA, e44); aB = mul2(aB, e44); }
            }
            float ylo, yhi; unpk2(y2, ylo, yhi);
            yp[(size_t)t * DD] = fmaf(uc, Dd, ylo + yhi);
            dtc = dtn; uc = un;
        }
    } else {
        for (int t = 0; t < CH; t++) {
            float dt = __ldg(dtp + (size_t)t * DD);
            float uu = __ldg(up + (size_t)t * DD);
            float dtu = dt * uu;
            u64 dtu2 = pk2(dtu, dtu);
            u64 y2 = 0ull;
#pragma unroll
            for (int p = 0; p < 8; p++) {
                u64 a2 = pk2(__expf(dt * Av[2 * p]), __expf(dt * Av[2 * p + 1]));
                u64 B2 = *(const u64*)&sBC[t][2 * p];
                u64 C2 = *(const u64*)&sBC[t][16 + 2 * p];
                h2[p] = fma2(a2, h2[p], mul2(dtu2, B2));
                y2 = fma2(h2[p], C2, y2);
            }
            float ylo, yhi; unpk2(y2, ylo, yhi);
            yp[(size_t)t * DD] = fmaf(uu, Dd, ylo + yhi);
        }
    }
}

// ================= launch =================
extern "C" void kernel_launch(void* const* d_in, const int* in_sizes, int n_in,
                              void* d_out, int out_size) {
    const float* u     = (const float*)d_in[0];
    const float* A_log = (const float*)d_in[1];
    const float* Dv    = (const float*)d_in[2];
    const float* Wx    = (const float*)d_in[3];
    const float* Wdt   = (const float*)d_in[4];
    const float* bdt   = (const float*)d_in[5];
    float* out = (float*)d_out;

    k_gemm1<<<dim3(32, KSPL), 256>>>(u, Wx);
    k_gemm2<<<dim3(32, 16), 256>>>(Wdt, bdt);
    k_scanA<<<dim3(DD / 256, NCH, BB), 256>>>(u, A_log);
    k_scanB<<<(BB * DD * NN) / 256, 256>>>(A_log);
    k_scanC<<<dim3(DD / 256, NCH, BB), 256>>>(u, A_log, Dv, out);
}

// round 15
// speedup vs baseline: 1.1268x; 1.0265x over previous
#include <cuda_runtime.h>
#include <cuda_bf16.h>
#include <math.h>

// Problem constants
#define BB 2
#define LL 2048
#define DD 2048
#define NN 16
#define KX 96          // DT_RANK + 2*D_STATE
#define NCH 64         // chunks along L
#define CH 32          // chunk length (NCH*CH == LL)
#define KSPL 8         // gemm1 K-split

typedef unsigned long long u64;

// ---------------- scratch (device globals) ----------------
__device__ __align__(16) float g_xpart[KSPL][BB * LL * KX];  // gemm1 K-split partials
__device__ __align__(16) float g_xdbl[BB * LL * KX];
__device__ __align__(16) float g_dt[BB * LL * DD];
__device__ __align__(16) float g_hf[BB * NCH * DD * NN];
__device__ __align__(16) float g_h0[BB * NCH * DD * NN];
__device__ __align__(16) float g_sdt[BB * NCH * DD];

// ---------------- f32x2 helpers ----------------
__device__ __forceinline__ u64 pk2(float lo, float hi) {
    u64 r; asm("mov.b64 %0,{%1,%2};" : "=l"(r) : "f"(lo), "f"(hi)); return r;
}
__device__ __forceinline__ void unpk2(u64 v, float& lo, float& hi) {
    asm("mov.b64 {%0,%1},%2;" : "=f"(lo), "=f"(hi) : "l"(v));
}
__device__ __forceinline__ u64 fma2(u64 a, u64 b, u64 c) {
    u64 d; asm("fma.rn.f32x2 %0,%1,%2,%3;" : "=l"(d) : "l"(a), "l"(b), "l"(c)); return d;
}
__device__ __forceinline__ u64 mul2(u64 a, u64 b) {
    u64 d; asm("mul.rn.f32x2 %0,%1,%2;" : "=l"(d) : "l"(a), "l"(b)); return d;
}

// ================= GEMM1 (K-split x8): 128-row tiles, micro 4rp x 6c, double-buffered, k-tile 16 =================
__global__ void __launch_bounds__(256) k_gemm1(const float* __restrict__ u,
                                               const float* __restrict__ Wx) {
    __shared__ __align__(16) u64 us2[2][16][65];
    __shared__ __align__(16) u64 ws2[2][16][97];
    const int r0 = blockIdx.x * 128;
    const int kbeg = blockIdx.y * 256;
    const int tid = threadIdx.x;
    const int tx = tid & 15, ty = tid >> 4;

    u64 acc[4][6];
#pragma unroll
    for (int i = 0; i < 4; i++)
#pragma unroll
        for (int j = 0; j < 6; j++) acc[i][j] = 0ull;

    auto stage = [&](int k0, int buf) {
        {
            int rp = tid >> 2;
            int kq = (tid & 3) * 4;
            const float4 a0 = *(const float4*)&u[(size_t)(r0 + 2 * rp) * 2048 + k0 + kq];
            const float4 a1 = *(const float4*)&u[(size_t)(r0 + 2 * rp + 1) * 2048 + k0 + kq];
            us2[buf][kq + 0][rp] = pk2(a0.x, a1.x);
            us2[buf][kq + 1][rp] = pk2(a0.y, a1.y);
            us2[buf][kq + 2][rp] = pk2(a0.z, a1.z);
            us2[buf][kq + 3][rp] = pk2(a0.w, a1.w);
        }
#pragma unroll
        for (int p = 0; p < 2; p++) {
            int g = tid + p * 256;
            if (g < 384) {
                int c = g >> 2;
                int kw = (g & 3) * 4;
                float4 w = *(const float4*)&Wx[(size_t)c * 2048 + k0 + kw];
                ws2[buf][kw + 0][c] = pk2(w.x, w.x);
                ws2[buf][kw + 1][c] = pk2(w.y, w.y);
                ws2[buf][kw + 2][c] = pk2(w.z, w.z);
                ws2[buf][kw + 3][c] = pk2(w.w, w.w);
            }
        }
    };

    stage(kbeg, 0);
    __syncthreads();
#pragma unroll
    for (int kt = 0; kt < 16; kt++) {
        if (kt < 15) stage(kbeg + (kt + 1) * 16, (kt + 1) & 1);
        const int buf = kt & 1;
#pragma unroll
        for (int k = 0; k < 16; k++) {
            u64 ua[4];
#pragma unroll
            for (int i = 0; i < 4; i++) ua[i] = us2[buf][k][ty * 4 + i];
#pragma unroll
            for (int j = 0; j < 6; j++) {
                u64 w2 = ws2[buf][k][tx * 6 + j];
#pragma unroll
                for (int i = 0; i < 4; i++) acc[i][j] = fma2(ua[i], w2, acc[i][j]);
            }
        }
        __syncthreads();
    }
    float* dst = g_xpart[blockIdx.y];
#pragma unroll
    for (int i = 0; i < 4; i++)
#pragma unroll
        for (int j = 0; j < 6; j++) {
            float lo, hi; unpk2(acc[i][j], lo, hi);
            int row = r0 + ty * 8 + 2 * i;
            int col = tx * 6 + j;
            dst[row * KX + col] = lo;
            dst[(row + 1) * KX + col] = hi;
        }
}

// ================= reduce the 8 partials (deterministic) =================
__global__ void __launch_bounds__(256) k_red1() {
    int idx = blockIdx.x * 256 + threadIdx.x;
    float4 s = ((const float4*)g_xpart[0])[idx];
#pragma unroll
    for (int p = 1; p < KSPL; p++) {
        float4 a = ((const float4*)g_xpart[p])[idx];
        s.x += a.x; s.y += a.y; s.z += a.z; s.w += a.w;
    }
    ((float4*)g_xdbl)[idx] = s;
}

// ========= GEMM2: 128x128 tile, micro 4rp x 8c =========
__global__ void __launch_bounds__(256) k_gemm2(const float* __restrict__ Wdt,
                                               const float* __restrict__ bdt) {
    __shared__ __align__(16) u64   us2[64][65];
    __shared__ __align__(16) float ws[64][128];
    const int r0 = blockIdx.x * 128;
    const int c0 = blockIdx.y * 128;
    const int tid = threadIdx.x;
    const int tx = tid & 15, ty = tid >> 4;

#pragma unroll
    for (int p = 0; p < 4; p++) {
        int g = tid + p * 256;
        int rp = g >> 4;
        int kq = (g & 15) * 4;
        const float4 a0 = *(const float4*)&g_xdbl[(r0 + 2 * rp) * KX + kq];
        const float4 a1 = *(const float4*)&g_xdbl[(r0 + 2 * rp + 1) * KX + kq];
        us2[kq + 0][rp] = pk2(a0.x, a1.x);
        us2[kq + 1][rp] = pk2(a0.y, a1.y);
        us2[kq + 2][rp] = pk2(a0.z, a1.z);
        us2[kq + 3][rp] = pk2(a0.w, a1.w);
    }
#pragma unroll
    for (int p = 0; p < 8; p++) {
        int g = tid + p * 256;
        int c = g & 127;
        int kq = (g >> 7) * 4;
        float4 w = *(const float4*)&Wdt[(size_t)(c0 + c) * 64 + kq];
        ws[kq + 0][c] = w.x;
        ws[kq + 1][c] = w.y;
        ws[kq + 2][c] = w.z;
        ws[kq + 3][c] = w.w;
    }
    __syncthreads();

    u64 acc[4][8];
#pragma unroll
    for (int i = 0; i < 4; i++)
#pragma unroll
        for (int j = 0; j < 8; j++) acc[i][j] = 0ull;

#pragma unroll 8
    for (int k = 0; k < 64; k++) {
        u64 ua[4];
#pragma unroll
        for (int i = 0; i < 4; i++) ua[i] = us2[k][ty * 4 + i];
        float4 wa = *(const float4*)&ws[k][tx * 8];
        float4 wb = *(const float4*)&ws[k][tx * 8 + 4];
        u64 w2[8] = {pk2(wa.x, wa.x), pk2(wa.y, wa.y), pk2(wa.z, wa.z), pk2(wa.w, wa.w),
                     pk2(wb.x, wb.x), pk2(wb.y, wb.y), pk2(wb.z, wb.z), pk2(wb.w, wb.w)};
#pragma unroll
        for (int j = 0; j < 8; j++)
#pragma unroll
            for (int i = 0; i < 4; i++) acc[i][j] = fma2(ua[i], w2[j], acc[i][j]);
    }

    float bb[8];
#pragma unroll
    for (int j = 0; j < 8; j++) bb[j] = bdt[c0 + tx * 8 + j];

#pragma unroll
    for (int i = 0; i < 4; i++)
#pragma unroll
        for (int j = 0; j < 8; j++) {
            float lo, hi; unpk2(acc[i][j], lo, hi);
            int row = r0 + ty * 8 + 2 * i;
            int col = c0 + tx * 8 + j;
            float x0 = lo + bb[j];
            float x1 = hi + bb[j];
            float s0 = fmaxf(x0, 0.f) + __logf(1.f + __expf(-fabsf(x0)));
            float s1 = fmaxf(x1, 0.f) + __logf(1.f + __expf(-fabsf(x1)));
            g_dt[(size_t)row * DD + col] = s0;
            g_dt[(size_t)(row + 1) * DD + col] = s1;
        }
}

// ---------------- per-thread A setup + structure check (float4 loads) ----------------
__device__ __forceinline__ bool load_A(const float* __restrict__ A_log, int d, float Av[16]) {
#pragma unroll
    for (int n = 0; n < 16; n += 4) {
        float4 a4 = *(const float4*)&A_log[d * 16 + n];
        Av[n]     = -__expf(a4.x);
        Av[n + 1] = -__expf(a4.y);
        Av[n + 2] = -__expf(a4.z);
        Av[n + 3] = -__expf(a4.w);
    }
    bool ok = (Av[0] < 0.f);
#pragma unroll
    for (int n = 1; n < 16; n++) {
        float tgt = (float)(n + 1) * Av[0];
        ok = ok && (fabsf(Av[n] - tgt) <= 4e-6f * fabsf(tgt));
    }
    return ok;
}

// ================= Scan phase A: local scan per chunk from h=0 (round-11 best) =================
__global__ void __launch_bounds__(256) k_scanA(const float* __restrict__ u,
                                               const float* __restrict__ A_log) {
    __shared__ __align__(16) float sB[CH][16];
    const int b = blockIdx.z, c = blockIdx.y;
    const int tid = threadIdx.x;
    const int d = blockIdx.x * 256 + tid;
    const int l0 = c * CH;

#pragma unroll
    for (int p = 0; p < 2; p++) {
        int idx = tid + p * 256;
        int t = idx >> 4, j = idx & 15;
        sB[t][j] = g_xdbl[(b * LL + l0 + t) * KX + 64 + j];
    }
    __syncthreads();

    float Av[16];
    const bool powok = load_A(A_log, d, Av);

    u64 h2[8];
#pragma unroll
    for (int p = 0; p < 8; p++) h2[p] = 0ull;
    float sdt = 0.f;

    const size_t base0 = (size_t)(b * LL + l0) * DD + d;
    const float* dtp = g_dt + base0;
    const float* up = u + base0;

    if (powok) {
        const float A0 = Av[0];
        float dtc = __ldg(dtp), uc = __ldg(up);
#pragma unroll 2
        for (int t = 0; t < CH; t++) {
            float dtn = 0.f, un = 0.f;
            if (t < CH - 1) {
                dtn = __ldg(dtp + (size_t)(t + 1) * DD);
                un  = __ldg(up + (size_t)(t + 1) * DD);
            }
            sdt += dtc;
            float e1 = __expf(A0 * dtc);
            float e2 = e1 * e1;
            float e4 = e2 * e2;
            u64 e44 = pk2(e4, e4);
            u64 aA = pk2(e1, e2);          // (e^1, e^2)
            u64 aB = mul2(aA, pk2(e2, e2)); // (e^3, e^4)
            float dtu = dtc * uc;
            u64 dtu2 = pk2(dtu, dtu);
#pragma unroll
            for (int p = 0; p < 8; p += 2) {
                u64 B2a = *(const u64*)&sB[t][2 * p];
                u64 B2b = *(const u64*)&sB[t][2 * p + 2];
                h2[p]     = fma2(aA, h2[p],     mul2(dtu2, B2a));
                h2[p + 1] = fma2(aB, h2[p + 1], mul2(dtu2, B2b));
                if (p < 6) { aA = mul2(aA, e44); aB = mul2(aB, e44); }
            }
            dtc = dtn; uc = un;
        }
    } else {
        for (int t = 0; t < CH; t++) {
            float dt = __ldg(dtp + (size_t)t * DD);
            float uu = __ldg(up + (size_t)t * DD);
            sdt += dt;
            float dtu = dt * uu;
            u64 dtu2 = pk2(dtu, dtu);
#pragma unroll
            for (int p = 0; p < 8; p++) {
                u64 a2 = pk2(__expf(dt * Av[2 * p]), __expf(dt * Av[2 * p + 1]));
                u64 B2 = *(const u64*)&sB[t][2 * p];
                h2[p] = fma2(a2, h2[p], mul2(dtu2, B2));
            }
        }
    }

    u64* hf = (u64*)(g_hf + ((size_t)((b * NCH + c) * DD) + d) * NN);
#pragma unroll
    for (int p = 0; p < 8; p++) hf[p] = h2[p];
    g_sdt[(b * NCH + c) * DD + d] = sdt;
}

// ================= Scan phase B: inter-chunk recurrence (4 chunks of 16, lower regs) =================
__global__ void __launch_bounds__(256) k_scanB(const float* __restrict__ A_log) {
    const int gid = blockIdx.x * 256 + threadIdx.x;  // < B*D*N = 65536
    const int b = gid >> 15;
    const int rem = gid & 32767;
    const int d = rem >> 4;
    const int n = rem & 15;
    const float A = -__expf(A_log[d * 16 + n]);

    float h = 0.f;
#pragma unroll
    for (int q = 0; q < 4; q++) {
        float av[16], fv[16];
#pragma unroll
        for (int i = 0; i < 16; i++) {
            int base = (b * NCH + q * 16 + i) * DD + d;
            av[i] = g_sdt[base];
            fv[i] = g_hf[(size_t)base * NN + n];
        }
#pragma unroll
        for (int i = 0; i < 16; i++) av[i] = __expf(A * av[i]);
#pragma unroll
        for (int i = 0; i < 16; i++) {
            int base = (b * NCH + q * 16 + i) * DD + d;
            g_h0[(size_t)base * NN + n] = h;
            h = fmaf(av[i], h, fv[i]);
        }
    }
}

// ================= Scan phase C: re-scan with correct h0, emit y (round-11 best) =================
__global__ void __launch_bounds__(256) k_scanC(const float* __restrict__ u,
                                               const float* __restrict__ A_log,
                                               const float* __restrict__ Dv,
                                               float* __restrict__ out) {
    __shared__ __align__(16) float sBC[CH][32];
    const int b = blockIdx.z, c = blockIdx.y;
    const int tid = threadIdx.x;
    const int d = blockIdx.x * 256 + tid;
    const int l0 = c * CH;

#pragma unroll
    for (int p = 0; p < 4; p++) {
        int idx = tid + p * 256;
        int t = idx >> 5, j = idx & 31;
        sBC[t][j] = g_xdbl[(b * LL + l0 + t) * KX + 64 + j];
    }
    __syncthreads();

    float Av[16];
    const bool powok = load_A(A_log, d, Av);
    const float Dd = Dv[d];

    u64 h2[8];
    {
        const u64* h0p = (const u64*)(g_h0 + ((size_t)((b * NCH + c) * DD) + d) * NN);
#pragma unroll
        for (int p = 0; p < 8; p++) h2[p] = h0p[p];
    }

    const size_t base0 = (size_t)(b * LL + l0) * DD + d;
    const float* dtp = g_dt + base0;
    const float* up = u + base0;
    float* yp = out + base0;

    if (powok) {
        const float A0 = Av[0];
        float dtc = __ldg(dtp), uc = __ldg(up);
#pragma unroll 2
        for (int t = 0; t < CH; t++) {
            float dtn = 0.f, un = 0.f;
            if (t < CH - 1) {
                dtn = __ldg(dtp + (size_t)(t + 1) * DD);
                un  = __ldg(up + (size_t)(t + 1) * DD);
            }
            float e1 = __expf(A0 * dtc);
            float e2 = e1 * e1;
            float e4 = e2 * e2;
            u64 e44 = pk2(e4, e4);
            u64 aA = pk2(e1, e2);
            u64 aB = mul2(aA, pk2(e2, e2));
            float dtu = dtc * uc;
            u64 dtu2 = pk2(dtu, dtu);
            u64 y2 = 0ull;
#pragma unroll
            for (int p = 0; p < 8; p += 2) {
                u64 B2a = *(const u64*)&sBC[t][2 * p];
                u64 B2b = *(const u64*)&sBC[t][2 * p + 2];
                u64 C2a = *(const u64*)&sBC[t][16 + 2 * p];
                u64 C2b = *(const u64*)&sBC[t][16 + 2 * p + 2];
                h2[p]     = fma2(aA, h2[p],     mul2(dtu2, B2a));
                h2[p + 1] = fma2(aB, h2[p + 1], mul2(dtu2, B2b));
                y2 = fma2(h2[p], C2a, y2);
                y2 = fma2(h2[p + 1], C2b, y2);
                if (p < 6) { aA = mul2(aA, e44); aB = mul2(aB, e44); }
            }
            float ylo, yhi; unpk2(y2, ylo, yhi);
            yp[(size_t)t * DD] = fmaf(uc, Dd, ylo + yhi);
            dtc = dtn; uc = un;
        }
    } else {
        for (int t = 0; t < CH; t++) {
            float dt = __ldg(dtp + (size_t)t * DD);
            float uu = __ldg(up + (size_t)t * DD);
            float dtu = dt * uu;
            u64 dtu2 = pk2(dtu, dtu);
            u64 y2 = 0ull;
#pragma unroll
            for (int p = 0; p < 8; p++) {
                u64 a2 = pk2(__expf(dt * Av[2 * p]), __expf(dt * Av[2 * p + 1]));
                u64 B2 = *(const u64*)&sBC[t][2 * p];
                u64 C2 = *(const u64*)&sBC[t][16 + 2 * p];
                h2[p] = fma2(a2, h2[p], mul2(dtu2, B2));
                y2 = fma2(h2[p], C2, y2);
            }
            float ylo, yhi; unpk2(y2, ylo, yhi);
            yp[(size_t)t * DD] = fmaf(uu, Dd, ylo + yhi);
        }
    }
}

// ================= launch =================
extern "C" void kernel_launch(void* const* d_in, const int* in_sizes, int n_in,
                              void* d_out, int out_size) {
    const float* u     = (const float*)d_in[0];
    const float* A_log = (const float*)d_in[1];
    const float* Dv    = (const float*)d_in[2];
    const float* Wx    = (const float*)d_in[3];
    const float* Wdt   = (const float*)d_in[4];
    const float* bdt   = (const float*)d_in[5];
    float* out = (float*)d_out;

    k_gemm1<<<dim3(32, KSPL), 256>>>(u, Wx);
    k_red1<<<384, 256>>>();
    k_gemm2<<<dim3(32, 16), 256>>>(Wdt, bdt);
    k_scanA<<<dim3(DD / 256, NCH, BB), 256>>>(u, A_log);
    k_scanB<<<(BB * DD * NN) / 256, 256>>>(A_log);
    k_scanC<<<dim3(DD / 256, NCH, BB), 256>>>(u, A_log, Dv, out);
}